// round 1
// baseline (speedup 1.0000x reference)
#include <cuda_runtime.h>
#include <math.h>

#define BB   128
#define SS   1024
#define TT   (BB*SS)          // 131072 tokens
#define IND  192
#define DD   64
#define EE   4
#define HID  256
#define NCLS 10

// ------------------------- scratch (device globals; no allocs) -------------
__device__ float g_h1[(size_t)TT * DD];      // gelu(x@W1+b1)
__device__ float g_h [(size_t)TT * DD];      // h1@W2+b2
__device__ float g_gate[TT];                 // top-1 gate value per token
__device__ int   g_idx[(size_t)EE * TT];     // per-expert token lists
__device__ int   g_cnt[EE];
__device__ float g_psum[EE];
__device__ float g_z[BB * DD];               // sum over S of moe_out

__device__ __forceinline__ float gelu_f(float v) {
    return 0.5f * v * (1.0f + erff(v * 0.70710678118654752440f));
}

// ------------------------- k0: zero accumulators ----------------------------
__global__ void k0_zero() {
    int t = threadIdx.x;
    for (int i = t; i < BB * DD; i += blockDim.x) g_z[i] = 0.0f;
    if (t < EE) { g_cnt[t] = 0; g_psum[t] = 0.0f; }
}

// ------------------------- k1: h1 = gelu(x @ W1 + b1) -----------------------
// [T,192] @ [192,64], tile 128 tokens x 64 outs, 256 threads, 8x4 per thread
__global__ void k1_pe1(const float* __restrict__ x,
                       const float* __restrict__ w1,
                       const float* __restrict__ b1) {
    __shared__ float xs[16][133];   // x^T chunk [k][token]
    __shared__ float ws[16][DD];    // W1 chunk  [k][out]

    const int t  = threadIdx.x;       // 256
    const int tx = t & 15;            // 4 outs
    const int ty = t >> 4;            // 8 tokens
    const int tok0 = blockIdx.x * 128;

    float acc[8][4];
#pragma unroll
    for (int r = 0; r < 8; ++r)
#pragma unroll
        for (int c = 0; c < 4; ++c) acc[r][c] = 0.0f;

    const int kk = t & 15;
    const int trow = t >> 4;

    for (int k0 = 0; k0 < IND; k0 += 16) {
#pragma unroll
        for (int p = 0; p < 8; ++p) {
            int tokl = p * 16 + trow;
            xs[kk][tokl] = x[(size_t)(tok0 + tokl) * IND + k0 + kk];
        }
#pragma unroll
        for (int p = 0; p < 4; ++p) {
            int idx = p * 256 + t;
            ws[idx >> 6][idx & 63] = w1[(k0 + (idx >> 6)) * DD + (idx & 63)];
        }
        __syncthreads();
#pragma unroll
        for (int k = 0; k < 16; ++k) {
            float4 w = *(const float4*)&ws[k][tx * 4];
#pragma unroll
            for (int r = 0; r < 8; ++r) {
                float a = xs[k][ty * 8 + r];
                acc[r][0] += a * w.x; acc[r][1] += a * w.y;
                acc[r][2] += a * w.z; acc[r][3] += a * w.w;
            }
        }
        __syncthreads();
    }

    float4 bb4 = *(const float4*)&b1[tx * 4];
#pragma unroll
    for (int r = 0; r < 8; ++r) {
        int tok = tok0 + ty * 8 + r;
        float4 v;
        v.x = gelu_f(acc[r][0] + bb4.x);
        v.y = gelu_f(acc[r][1] + bb4.y);
        v.z = gelu_f(acc[r][2] + bb4.z);
        v.w = gelu_f(acc[r][3] + bb4.w);
        *(float4*)&g_h1[(size_t)tok * DD + tx * 4] = v;
    }
}

// ------------------- k2: h = h1 @ W2 + b2, fused gate -----------------------
// tile 64 tokens x 64 outs, 256 threads, 4x4 per thread
__global__ void k2_pe2_gate(const float* __restrict__ w2,
                            const float* __restrict__ b2,
                            const float* __restrict__ gw,
                            const float* __restrict__ gb) {
    __shared__ float xsT[64 * 65];   // h1^T [k][tok]; reused as hs[tok*65+d]
    __shared__ float ws[64 * 64];
    __shared__ float sps[EE];

    const int t  = threadIdx.x;
    const int tx = t & 15;
    const int ty = t >> 4;
    const int tok0 = blockIdx.x * 64;

    {
        int k = t & 63, tb = t >> 6;
#pragma unroll
        for (int p = 0; p < 16; ++p) {
            int tokl = p * 4 + tb;
            xsT[k * 65 + tokl] = g_h1[(size_t)(tok0 + tokl) * DD + k];
        }
    }
#pragma unroll
    for (int p = 0; p < 16; ++p) {
        int idx = p * 256 + t;
        ws[idx] = w2[idx];
    }
    if (t < EE) sps[t] = 0.0f;
    __syncthreads();

    float acc[4][4];
#pragma unroll
    for (int r = 0; r < 4; ++r)
#pragma unroll
        for (int c = 0; c < 4; ++c) acc[r][c] = 0.0f;

#pragma unroll 16
    for (int k = 0; k < 64; ++k) {
        float4 w = *(const float4*)&ws[k * 64 + tx * 4];
#pragma unroll
        for (int r = 0; r < 4; ++r) {
            float a = xsT[k * 65 + ty * 4 + r];
            acc[r][0] += a * w.x; acc[r][1] += a * w.y;
            acc[r][2] += a * w.z; acc[r][3] += a * w.w;
        }
    }
    __syncthreads();   // done reading xsT; reuse as hs

    float4 bb4 = *(const float4*)&b2[tx * 4];
#pragma unroll
    for (int r = 0; r < 4; ++r) {
        int tokl = ty * 4 + r;
        float v0 = acc[r][0] + bb4.x, v1 = acc[r][1] + bb4.y;
        float v2 = acc[r][2] + bb4.z, v3 = acc[r][3] + bb4.w;
        float4 v; v.x = v0; v.y = v1; v.z = v2; v.w = v3;
        *(float4*)&g_h[(size_t)(tok0 + tokl) * DD + tx * 4] = v;
        xsT[tokl * 65 + tx * 4 + 0] = v0;
        xsT[tokl * 65 + tx * 4 + 1] = v1;
        xsT[tokl * 65 + tx * 4 + 2] = v2;
        xsT[tokl * 65 + tx * 4 + 3] = v3;
    }
    __syncthreads();

    if (t < 64) {
        int tok = tok0 + t;
        float lg0 = gb[0], lg1 = gb[1], lg2 = gb[2], lg3 = gb[3];
#pragma unroll 16
        for (int d = 0; d < 64; ++d) {
            float h = xsT[t * 65 + d];
            float4 g4 = *(const float4*)&gw[d * 4];
            lg0 += h * g4.x; lg1 += h * g4.y; lg2 += h * g4.z; lg3 += h * g4.w;
        }
        float m = fmaxf(fmaxf(lg0, lg1), fmaxf(lg2, lg3));
        float e0 = expf(lg0 - m), e1 = expf(lg1 - m), e2 = expf(lg2 - m), e3 = expf(lg3 - m);
        float inv = 1.0f / (e0 + e1 + e2 + e3);
        float p0 = e0 * inv, p1 = e1 * inv, p2 = e2 * inv, p3 = e3 * inv;
        int am = 0; float best = lg0;
        if (lg1 > best) { best = lg1; am = 1; }
        if (lg2 > best) { best = lg2; am = 2; }
        if (lg3 > best) { best = lg3; am = 3; }
        float pe[4] = {p0, p1, p2, p3};
        g_gate[tok] = pe[am];
        int pos = atomicAdd(&g_cnt[am], 1);
        g_idx[(size_t)am * TT + pos] = tok;
        atomicAdd(&sps[0], p0); atomicAdd(&sps[1], p1);
        atomicAdd(&sps[2], p2); atomicAdd(&sps[3], p3);
    }
    __syncthreads();
    if (t < EE) atomicAdd(&g_psum[t], sps[t]);
}

// ------------------- k3: per-expert fused FFN (gathered) --------------------
// block handles up to 64 tokens of expert blockIdx.y; hidden done in 64-chunks
__global__ void k3_expert(const float* __restrict__ ew1,
                          const float* __restrict__ eb1,
                          const float* __restrict__ ew2,
                          const float* __restrict__ eb2) {
    const int e    = blockIdx.y;
    const int base = blockIdx.x * 64;
    const int cnt  = g_cnt[e];
    if (base >= cnt) return;
    const int n = min(64, cnt - base);

    __shared__ float hsT[64 * 65];   // h^T  [k][tok]
    __shared__ float hcT[64 * 65];   // Hchunk^T [j][tok]
    __shared__ int   stok[64];
    __shared__ float sgate[64];

    const int t  = threadIdx.x;     // 256
    const int tx = t & 15;
    const int ty = t >> 4;

    if (t < 64) {
        if (t < n) {
            int tok = g_idx[(size_t)e * TT + base + t];
            stok[t]  = tok;
            sgate[t] = g_gate[tok];
        } else {
            stok[t] = -1; sgate[t] = 0.0f;
        }
    }
    __syncthreads();

    {   // gather h rows into hsT (transposed)
        int tokl = t >> 2;
        int part = t & 3;
        int tok = stok[tokl];
#pragma unroll
        for (int q = 0; q < 4; ++q) {
            float4 v = make_float4(0.f, 0.f, 0.f, 0.f);
            if (tok >= 0)
                v = *(const float4*)&g_h[(size_t)tok * DD + part * 16 + q * 4];
            int kb = part * 16 + q * 4;
            hsT[(kb + 0) * 65 + tokl] = v.x;
            hsT[(kb + 1) * 65 + tokl] = v.y;
            hsT[(kb + 2) * 65 + tokl] = v.z;
            hsT[(kb + 3) * 65 + tokl] = v.w;
        }
    }
    __syncthreads();

    const float* w1e = ew1 + (size_t)e * DD * HID;
    const float* w2e = ew2 + (size_t)e * HID * DD;
    const float* b1e = eb1 + (size_t)e * HID;
    const float* b2e = eb2 + (size_t)e * DD;

    float acc2[4][4];
#pragma unroll
    for (int r = 0; r < 4; ++r)
#pragma unroll
        for (int c = 0; c < 4; ++c) acc2[r][c] = 0.0f;

    for (int ch = 0; ch < HID / 64; ++ch) {
        // GEMM1 chunk: Hc[tok][j] = gelu(sum_k h[tok][k]*W1e[k][ch*64+j] + b1)
        float acc1[4][4];
#pragma unroll
        for (int r = 0; r < 4; ++r)
#pragma unroll
            for (int c = 0; c < 4; ++c) acc1[r][c] = 0.0f;

#pragma unroll 16
        for (int k = 0; k < 64; ++k) {
            float4 w = *(const float4*)&w1e[(size_t)k * HID + ch * 64 + tx * 4];
#pragma unroll
            for (int r = 0; r < 4; ++r) {
                float a = hsT[k * 65 + ty * 4 + r];
                acc1[r][0] += a * w.x; acc1[r][1] += a * w.y;
                acc1[r][2] += a * w.z; acc1[r][3] += a * w.w;
            }
        }
        __syncthreads();  // previous hcT fully consumed
        float4 bb4 = *(const float4*)&b1e[ch * 64 + tx * 4];
#pragma unroll
        for (int r = 0; r < 4; ++r) {
            int tokl = ty * 4 + r;
            hcT[(tx * 4 + 0) * 65 + tokl] = gelu_f(acc1[r][0] + bb4.x);
            hcT[(tx * 4 + 1) * 65 + tokl] = gelu_f(acc1[r][1] + bb4.y);
            hcT[(tx * 4 + 2) * 65 + tokl] = gelu_f(acc1[r][2] + bb4.z);
            hcT[(tx * 4 + 3) * 65 + tokl] = gelu_f(acc1[r][3] + bb4.w);
        }
        __syncthreads();

        // GEMM2 chunk: out[tok][d] += sum_j Hc[tok][j]*W2e[ch*64+j][d]
#pragma unroll 16
        for (int j = 0; j < 64; ++j) {
            float4 w = *(const float4*)&w2e[(size_t)(ch * 64 + j) * DD + tx * 4];
#pragma unroll
            for (int r = 0; r < 4; ++r) {
                float a = hcT[j * 65 + ty * 4 + r];
                acc2[r][0] += a * w.x; acc2[r][1] += a * w.y;
                acc2[r][2] += a * w.z; acc2[r][3] += a * w.w;
            }
        }
    }

    float4 bb4 = *(const float4*)&b2e[tx * 4];
#pragma unroll
    for (int r = 0; r < 4; ++r) {
        int tokl = ty * 4 + r;
        if (tokl < n) {
            int tok = stok[tokl];
            float gv = sgate[tokl];
            int b = tok >> 10;   // tok / S
            atomicAdd(&g_z[b * DD + tx * 4 + 0], (acc2[r][0] + bb4.x) * gv);
            atomicAdd(&g_z[b * DD + tx * 4 + 1], (acc2[r][1] + bb4.y) * gv);
            atomicAdd(&g_z[b * DD + tx * 4 + 2], (acc2[r][2] + bb4.z) * gv);
            atomicAdd(&g_z[b * DD + tx * 4 + 3], (acc2[r][3] + bb4.w) * gv);
        }
    }
}

// ------------------- k4: LayerNorm + classifier + aux loss ------------------
__global__ void k4_cls(const float* __restrict__ lng, const float* __restrict__ lnb,
                       const float* __restrict__ w1,  const float* __restrict__ b1,
                       const float* __restrict__ w2,  const float* __restrict__ b2,
                       float* __restrict__ out, int out_size) {
    int b = threadIdx.x;   // 128
    float zr[DD];
    float s = 0.0f;
#pragma unroll
    for (int d = 0; d < DD; ++d) {
        float v = g_z[b * DD + d] * (1.0f / (float)SS);
        zr[d] = v; s += v;
    }
    float mu = s * (1.0f / DD);
    float ss2 = 0.0f;
#pragma unroll
    for (int d = 0; d < DD; ++d) { float c = zr[d] - mu; ss2 += c * c; }
    float inv = rsqrtf(ss2 * (1.0f / DD) + 1e-5f);
#pragma unroll
    for (int d = 0; d < DD; ++d)
        zr[d] = (zr[d] - mu) * inv * lng[d] + lnb[d];

    float h[DD];
#pragma unroll
    for (int o = 0; o < DD; ++o) h[o] = b1[o];
    for (int d = 0; d < DD; ++d) {
        float zd = zr[d];
#pragma unroll
        for (int o = 0; o < DD; ++o) h[o] += zd * w1[d * DD + o];
    }
#pragma unroll
    for (int o = 0; o < DD; ++o) h[o] = gelu_f(h[o]);

    float y[NCLS];
#pragma unroll
    for (int c = 0; c < NCLS; ++c) y[c] = b2[c];
    for (int o = 0; o < DD; ++o) {
        float ho = h[o];
#pragma unroll
        for (int c = 0; c < NCLS; ++c) y[c] += ho * w2[o * NCLS + c];
    }
#pragma unroll
    for (int c = 0; c < NCLS; ++c) out[b * NCLS + c] = y[c];

    if (b == 0) {
        float aux = 0.0f;
        for (int e = 0; e < EE; ++e) {
            float f = (float)g_cnt[e] / (float)TT;
            float p = g_psum[e] / (float)TT;
            aux += f * p;
        }
        out[out_size - 1] = (float)EE * aux;
    }
}

// ----------------------------- launch ---------------------------------------
extern "C" void kernel_launch(void* const* d_in, const int* in_sizes, int n_in,
                              void* d_out, int out_size) {
    const float* x      = (const float*)d_in[0];
    const float* pe_w1  = (const float*)d_in[1];
    const float* pe_b1  = (const float*)d_in[2];
    const float* pe_w2  = (const float*)d_in[3];
    const float* pe_b2  = (const float*)d_in[4];
    const float* gate_w = (const float*)d_in[5];
    const float* gate_b = (const float*)d_in[6];
    const float* ew1    = (const float*)d_in[7];
    const float* eb1    = (const float*)d_in[8];
    const float* ew2    = (const float*)d_in[9];
    const float* eb2    = (const float*)d_in[10];
    const float* ln_g   = (const float*)d_in[11];
    const float* ln_b   = (const float*)d_in[12];
    const float* cl_w1  = (const float*)d_in[13];
    const float* cl_b1  = (const float*)d_in[14];
    const float* cl_w2  = (const float*)d_in[15];
    const float* cl_b2  = (const float*)d_in[16];

    k0_zero<<<1, 256>>>();
    k1_pe1<<<TT / 128, 256>>>(x, pe_w1, pe_b1);
    k2_pe2_gate<<<TT / 64, 256>>>(pe_w2, pe_b2, gate_w, gate_b);
    k3_expert<<<dim3(TT / 64, EE), 256>>>(ew1, eb1, ew2, eb2);
    k4_cls<<<1, 128>>>(ln_g, ln_b, cl_w1, cl_b1, cl_w2, cl_b2,
                       (float*)d_out, out_size);
}

// round 3
// speedup vs baseline: 1.0516x; 1.0516x over previous
#include <cuda_runtime.h>
#include <math.h>

#define BB   128
#define SS   1024
#define TT   (BB*SS)          // 131072 tokens
#define IND  192
#define DD   64
#define EE   4
#define HID  256
#define NCLS 10

#define PA2 34   // k1 x-tile pitch in float2 (32 + 2)
#define PH2 66   // 64-wide activation pitch in float2
#define PW2 66   // 64-wide weight pitch in float2

// ------------------------- scratch (device globals) ------------------------
__device__ float g_h1[(size_t)TT * DD];      // h1; later reused as moe output
__device__ float g_h [(size_t)TT * DD];      // h = h1@W2+b2
__device__ float g_gate[TT];
__device__ int   g_idx[(size_t)EE * TT];
__device__ int   g_cnt[EE];
__device__ float g_psum[EE];
__device__ float g_z[BB * DD];               // mean over S of moe_out

__device__ __forceinline__ float gelu_f(float v) {
    return 0.5f * v * (1.0f + erff(v * 0.70710678118654752440f));
}
// split fp32 into tf32 hi + tf32 lo (tf32x3 emulation operands)
__device__ __forceinline__ float2 split_tf(float f) {
    unsigned hu, lu;
    asm("cvt.rna.tf32.f32 %0, %1;" : "=r"(hu) : "f"(f));
    float hi = __uint_as_float(hu);
    asm("cvt.rna.tf32.f32 %0, %1;" : "=r"(lu) : "f"(f - hi));
    return make_float2(hi, __uint_as_float(lu));
}
__device__ __forceinline__ void mma8(float* c, const unsigned* a, unsigned b0, unsigned b1) {
    asm volatile(
        "mma.sync.aligned.m16n8k8.row.col.f32.tf32.tf32.f32 "
        "{%0,%1,%2,%3},{%4,%5,%6,%7},{%8,%9},{%0,%1,%2,%3};"
        : "+f"(c[0]), "+f"(c[1]), "+f"(c[2]), "+f"(c[3])
        : "r"(a[0]), "r"(a[1]), "r"(a[2]), "r"(a[3]), "r"(b0), "r"(b1));
}
// tf32x3: acc += al*bh + ah*bl + ah*bh
__device__ __forceinline__ void mma3(float* c, const unsigned* ah, const unsigned* al,
                                     unsigned bh0, unsigned bh1, unsigned bl0, unsigned bl1) {
    mma8(c, al, bh0, bh1);
    mma8(c, ah, bl0, bl1);
    mma8(c, ah, bh0, bh1);
}
// A fragment (m16k8 row-major) hi+lo from float2 smem
__device__ __forceinline__ void ldA2(unsigned* ah, unsigned* al,
                                     const float2* base, int pitch, int g, int tg) {
    float2 v0 = base[g * pitch + tg];
    float2 v1 = base[(g + 8) * pitch + tg];
    float2 v2 = base[g * pitch + tg + 4];
    float2 v3 = base[(g + 8) * pitch + tg + 4];
    ah[0] = __float_as_uint(v0.x); al[0] = __float_as_uint(v0.y);
    ah[1] = __float_as_uint(v1.x); al[1] = __float_as_uint(v1.y);
    ah[2] = __float_as_uint(v2.x); al[2] = __float_as_uint(v2.y);
    ah[3] = __float_as_uint(v3.x); al[3] = __float_as_uint(v3.y);
}

// ------------------------- k0: zero counters -------------------------------
__global__ void k0_zero() {
    int t = threadIdx.x;
    if (t < EE) { g_cnt[t] = 0; g_psum[t] = 0.0f; }
}

// ------------------------- k1: h1 = gelu(x @ W1 + b1) ----------------------
// 128 tokens x 64 outs per block, K=192 in 32-chunks, 8 warps (16 rows each)
// dyn smem: xs float2[128*PA2] | ws float2[32*PW2]
extern __shared__ float2 sm1[];
__global__ void __launch_bounds__(256) k1_pe1(const float* __restrict__ x,
                                              const float* __restrict__ w1,
                                              const float* __restrict__ b1) {
    float2* xs = sm1;
    float2* ws = sm1 + 128 * PA2;

    const int t = threadIdx.x, lane = t & 31, w = t >> 5;
    const int g = lane >> 2, tg = lane & 3;
    const int tok0 = blockIdx.x * 128;
    const int row0 = w * 16;

    float acc[8][4];
#pragma unroll
    for (int j = 0; j < 8; ++j)
#pragma unroll
        for (int c = 0; c < 4; ++c) acc[j][c] = 0.0f;

    for (int k0 = 0; k0 < IND; k0 += 32) {
        {   // stage x chunk [128][32] split
            int row = t >> 1, cb = (t & 1) * 16;
            const float* src = x + (size_t)(tok0 + row) * IND + k0 + cb;
            float2* dst = xs + row * PA2 + cb;
#pragma unroll
            for (int q = 0; q < 4; ++q) {
                float4 v = *(const float4*)(src + q * 4);
                dst[q * 4 + 0] = split_tf(v.x);
                dst[q * 4 + 1] = split_tf(v.y);
                dst[q * 4 + 2] = split_tf(v.z);
                dst[q * 4 + 3] = split_tf(v.w);
            }
        }
#pragma unroll
        for (int p = 0; p < 8; ++p) {   // stage w1 chunk [32][64] split
            int idx = p * 256 + t;
            int kk = idx >> 6, nn = idx & 63;
            ws[kk * PW2 + nn] = split_tf(w1[(size_t)(k0 + kk) * DD + nn]);
        }
        __syncthreads();

#pragma unroll
        for (int ks = 0; ks < 32; ks += 8) {
            unsigned ah[4], al[4];
            ldA2(ah, al, xs + row0 * PA2 + ks, PA2, g, tg);
#pragma unroll
            for (int j = 0; j < 8; ++j) {
                float2 wb0 = ws[(ks + tg) * PW2 + j * 8 + g];
                float2 wb1 = ws[(ks + tg + 4) * PW2 + j * 8 + g];
                mma3(acc[j], ah, al,
                     __float_as_uint(wb0.x), __float_as_uint(wb1.x),
                     __float_as_uint(wb0.y), __float_as_uint(wb1.y));
            }
        }
        __syncthreads();
    }

#pragma unroll
    for (int j = 0; j < 8; ++j) {
        int n0 = j * 8;
        float bx = __ldg(&b1[n0 + 2 * tg]);
        float by = __ldg(&b1[n0 + 2 * tg + 1]);
        int r0 = tok0 + row0 + g;
        float2 v0, v1;
        v0.x = gelu_f(acc[j][0] + bx); v0.y = gelu_f(acc[j][1] + by);
        v1.x = gelu_f(acc[j][2] + bx); v1.y = gelu_f(acc[j][3] + by);
        *(float2*)&g_h1[(size_t)r0 * DD + n0 + 2 * tg]       = v0;
        *(float2*)&g_h1[(size_t)(r0 + 8) * DD + n0 + 2 * tg] = v1;
    }
}

// ------------------- k2: h = h1 @ W2 + b2, fused gate ----------------------
// 64 tokens per block; 8 warps as 4(m) x 2(n)
// dyn smem: hs float2[64*PH2] | ws float2[64*PW2]; hs region reused as fp32 h
extern __shared__ float2 sm2[];
__global__ void __launch_bounds__(256) k2_pe2_gate(const float* __restrict__ w2,
                                                   const float* __restrict__ b2,
                                                   const float* __restrict__ gw,
                                                   const float* __restrict__ gb) {
    float2* hs = sm2;
    float2* ws = sm2 + 64 * PH2;
    float*  hsf = (float*)sm2;           // alias, used after GEMM
    __shared__ float sps[EE];

    const int t = threadIdx.x, lane = t & 31, w = t >> 5;
    const int g = lane >> 2, tg = lane & 3;
    const int row0 = (w & 3) * 16;
    const int nb = (w >> 2) * 32;
    const int tok0 = blockIdx.x * 64;

    {   // stage h1 tile [64][64] split
        int row = t >> 2, cb = (t & 3) * 16;
        const float* src = g_h1 + (size_t)(tok0 + row) * DD + cb;
        float2* dst = hs + row * PH2 + cb;
#pragma unroll
        for (int q = 0; q < 4; ++q) {
            float4 v = *(const float4*)(src + q * 4);
            dst[q * 4 + 0] = split_tf(v.x);
            dst[q * 4 + 1] = split_tf(v.y);
            dst[q * 4 + 2] = split_tf(v.z);
            dst[q * 4 + 3] = split_tf(v.w);
        }
    }
#pragma unroll
    for (int p = 0; p < 16; ++p) {   // stage w2 [64][64] split
        int idx = p * 256 + t;
        int kk = idx >> 6, nn = idx & 63;
        ws[kk * PW2 + nn] = split_tf(w2[(size_t)kk * DD + nn]);
    }
    if (t < EE) sps[t] = 0.0f;
    __syncthreads();

    float acc[4][4];
#pragma unroll
    for (int j = 0; j < 4; ++j)
#pragma unroll
        for (int c = 0; c < 4; ++c) acc[j][c] = 0.0f;

#pragma unroll
    for (int ks = 0; ks < 64; ks += 8) {
        unsigned ah[4], al[4];
        ldA2(ah, al, hs + row0 * PH2 + ks, PH2, g, tg);
#pragma unroll
        for (int j = 0; j < 4; ++j) {
            float2 wb0 = ws[(ks + tg) * PW2 + nb + j * 8 + g];
            float2 wb1 = ws[(ks + tg + 4) * PW2 + nb + j * 8 + g];
            mma3(acc[j], ah, al,
                 __float_as_uint(wb0.x), __float_as_uint(wb1.x),
                 __float_as_uint(wb0.y), __float_as_uint(wb1.y));
        }
    }
    __syncthreads();   // done reading hs/ws; reuse hsf for fp32 h

#pragma unroll
    for (int j = 0; j < 4; ++j) {
        int n0 = nb + j * 8;
        float bx = __ldg(&b2[n0 + 2 * tg]);
        float by = __ldg(&b2[n0 + 2 * tg + 1]);
        float h00 = acc[j][0] + bx, h01 = acc[j][1] + by;
        float h10 = acc[j][2] + bx, h11 = acc[j][3] + by;
        int r = row0 + g;
        float2 v0; v0.x = h00; v0.y = h01;
        float2 v1; v1.x = h10; v1.y = h11;
        *(float2*)&g_h[(size_t)(tok0 + r) * DD + n0 + 2 * tg]     = v0;
        *(float2*)&g_h[(size_t)(tok0 + r + 8) * DD + n0 + 2 * tg] = v1;
        hsf[r * 65 + n0 + 2 * tg] = h00;       hsf[r * 65 + n0 + 2 * tg + 1] = h01;
        hsf[(r + 8) * 65 + n0 + 2 * tg] = h10; hsf[(r + 8) * 65 + n0 + 2 * tg + 1] = h11;
    }
    __syncthreads();

    if (t < 64) {
        int tok = tok0 + t;
        float lg0 = gb[0], lg1 = gb[1], lg2 = gb[2], lg3 = gb[3];
#pragma unroll 16
        for (int d = 0; d < 64; ++d) {
            float h = hsf[t * 65 + d];
            float4 g4 = *(const float4*)&gw[d * 4];
            lg0 += h * g4.x; lg1 += h * g4.y; lg2 += h * g4.z; lg3 += h * g4.w;
        }
        float m = fmaxf(fmaxf(lg0, lg1), fmaxf(lg2, lg3));
        float e0 = expf(lg0 - m), e1 = expf(lg1 - m);
        float e2 = expf(lg2 - m), e3 = expf(lg3 - m);
        float inv = 1.0f / (e0 + e1 + e2 + e3);
        float p0 = e0 * inv, p1 = e1 * inv, p2 = e2 * inv, p3 = e3 * inv;
        int am = 0; float best = lg0;
        if (lg1 > best) { best = lg1; am = 1; }
        if (lg2 > best) { best = lg2; am = 2; }
        if (lg3 > best) { best = lg3; am = 3; }
        float pe[4] = {p0, p1, p2, p3};
        g_gate[tok] = pe[am];
        int pos = atomicAdd(&g_cnt[am], 1);
        g_idx[(size_t)am * TT + pos] = tok;
        atomicAdd(&sps[0], p0); atomicAdd(&sps[1], p1);
        atomicAdd(&sps[2], p2); atomicAdd(&sps[3], p3);
    }
    __syncthreads();
    if (t < EE) atomicAdd(&g_psum[t], sps[t]);
}

// ------------------- k3: per-expert fused FFN (tf32x3, gathered) -----------
// 64 tokens per block, hidden in 64-wide chunks; 8 warps as 4(m) x 2(n)
// dyn smem: hs fl2[64*PH2] | hc fl2[64*PH2] | ws fl2[64*PW2] | stok[64]|sgate[64]
extern __shared__ float2 sm3[];
__global__ void __launch_bounds__(256) k3_expert(const float* __restrict__ ew1,
                                                 const float* __restrict__ eb1,
                                                 const float* __restrict__ ew2,
                                                 const float* __restrict__ eb2) {
    const int e = blockIdx.y;
    const int base = blockIdx.x * 64;
    const int cnt = g_cnt[e];
    if (base >= cnt) return;
    const int n = min(64, cnt - base);

    float2* hs = sm3;
    float2* hc = sm3 + 64 * PH2;
    float2* ws = sm3 + 2 * 64 * PH2;
    int*   stok  = (int*)(sm3 + 2 * 64 * PH2 + 64 * PW2);
    float* sgate = (float*)(stok + 64);

    const int t = threadIdx.x, lane = t & 31, w = t >> 5;
    const int g = lane >> 2, tg = lane & 3;
    const int row0 = (w & 3) * 16;
    const int nb = (w >> 2) * 32;

    if (t < 64) {
        if (t < n) {
            int tok = g_idx[(size_t)e * TT + base + t];
            stok[t] = tok;
            sgate[t] = g_gate[tok];
        } else { stok[t] = -1; sgate[t] = 0.0f; }
    }
    __syncthreads();

    {   // gather h rows, split
        int tokl = t >> 2, part = (t & 3) * 16;
        int tok = stok[tokl];
        float2* dst = hs + tokl * PH2 + part;
        if (tok >= 0) {
            const float* src = g_h + (size_t)tok * DD + part;
#pragma unroll
            for (int q = 0; q < 4; ++q) {
                float4 v = *(const float4*)(src + q * 4);
                dst[q * 4 + 0] = split_tf(v.x);
                dst[q * 4 + 1] = split_tf(v.y);
                dst[q * 4 + 2] = split_tf(v.z);
                dst[q * 4 + 3] = split_tf(v.w);
            }
        } else {
#pragma unroll
            for (int q = 0; q < 16; ++q) dst[q] = make_float2(0.f, 0.f);
        }
    }

    const float* w1e = ew1 + (size_t)e * DD * HID;
    const float* w2e = ew2 + (size_t)e * HID * DD;
    const float* b1e = eb1 + (size_t)e * HID;
    const float* b2e = eb2 + (size_t)e * DD;

    float acc2[4][4];
#pragma unroll
    for (int j = 0; j < 4; ++j)
#pragma unroll
        for (int c = 0; c < 4; ++c) acc2[j][c] = 0.0f;

    for (int ch = 0; ch < HID / 64; ++ch) {
        __syncthreads();   // gather done / prev GEMM2 done with ws
#pragma unroll
        for (int p = 0; p < 16; ++p) {   // stage W1 chunk [64 k][64 n] split
            int idx = p * 256 + t;
            int kk = idx >> 6, nn = idx & 63;
            ws[kk * PW2 + nn] = split_tf(w1e[(size_t)kk * HID + ch * 64 + nn]);
        }
        __syncthreads();

        float acc1[4][4];
#pragma unroll
        for (int j = 0; j < 4; ++j)
#pragma unroll
            for (int c = 0; c < 4; ++c) acc1[j][c] = 0.0f;

#pragma unroll
        for (int ks = 0; ks < 64; ks += 8) {
            unsigned ah[4], al[4];
            ldA2(ah, al, hs + row0 * PH2 + ks, PH2, g, tg);
#pragma unroll
            for (int j = 0; j < 4; ++j) {
                float2 wb0 = ws[(ks + tg) * PW2 + nb + j * 8 + g];
                float2 wb1 = ws[(ks + tg + 4) * PW2 + nb + j * 8 + g];
                mma3(acc1[j], ah, al,
                     __float_as_uint(wb0.x), __float_as_uint(wb1.x),
                     __float_as_uint(wb0.y), __float_as_uint(wb1.y));
            }
        }
        __syncthreads();   // GEMM1 done reading ws; hc free (prev GEMM2 done)

#pragma unroll
        for (int j = 0; j < 4; ++j) {   // gelu -> hc (split)
            int n0 = nb + j * 8;
            float bx = __ldg(&b1e[ch * 64 + n0 + 2 * tg]);
            float by = __ldg(&b1e[ch * 64 + n0 + 2 * tg + 1]);
            int r = row0 + g;
            hc[r * PH2 + n0 + 2 * tg]           = split_tf(gelu_f(acc1[j][0] + bx));
            hc[r * PH2 + n0 + 2 * tg + 1]       = split_tf(gelu_f(acc1[j][1] + by));
            hc[(r + 8) * PH2 + n0 + 2 * tg]     = split_tf(gelu_f(acc1[j][2] + bx));
            hc[(r + 8) * PH2 + n0 + 2 * tg + 1] = split_tf(gelu_f(acc1[j][3] + by));
        }
#pragma unroll
        for (int p = 0; p < 16; ++p) {   // stage W2 chunk [64 j][64 d] split
            int idx = p * 256 + t;
            int jj = idx >> 6, nn = idx & 63;
            ws[jj * PW2 + nn] = split_tf(w2e[(size_t)(ch * 64 + jj) * DD + nn]);
        }
        __syncthreads();

#pragma unroll
        for (int ks = 0; ks < 64; ks += 8) {
            unsigned ah[4], al[4];
            ldA2(ah, al, hc + row0 * PH2 + ks, PH2, g, tg);
#pragma unroll
            for (int j = 0; j < 4; ++j) {
                float2 wb0 = ws[(ks + tg) * PW2 + nb + j * 8 + g];
                float2 wb1 = ws[(ks + tg + 4) * PW2 + nb + j * 8 + g];
                mma3(acc2[j], ah, al,
                     __float_as_uint(wb0.x), __float_as_uint(wb1.x),
                     __float_as_uint(wb0.y), __float_as_uint(wb1.y));
            }
        }
    }

    // scatter per-token moe output (scaled by gate) into g_h1 (reused)
#pragma unroll
    for (int j = 0; j < 4; ++j) {
        int n0 = nb + j * 8;
        float bx = __ldg(&b2e[n0 + 2 * tg]);
        float by = __ldg(&b2e[n0 + 2 * tg + 1]);
        int r = row0 + g;
        if (stok[r] >= 0) {
            int tok = stok[r]; float gv = sgate[r];
            float2 v; v.x = (acc2[j][0] + bx) * gv; v.y = (acc2[j][1] + by) * gv;
            *(float2*)&g_h1[(size_t)tok * DD + n0 + 2 * tg] = v;
        }
        if (stok[r + 8] >= 0) {
            int tok = stok[r + 8]; float gv = sgate[r + 8];
            float2 v; v.x = (acc2[j][2] + bx) * gv; v.y = (acc2[j][3] + by) * gv;
            *(float2*)&g_h1[(size_t)tok * DD + n0 + 2 * tg] = v;
        }
    }
}

// ------------------- k3b: deterministic mean over S ------------------------
__global__ void __launch_bounds__(256) k3b_reduce() {
    __shared__ float red[4][64];
    int b = blockIdx.x, t = threadIdx.x;
    int d = t & 63, grp = t >> 6;
    const float* src = g_h1 + (size_t)b * SS * DD;
    float s = 0.0f;
    for (int i = grp * 256; i < grp * 256 + 256; ++i)
        s += src[(size_t)i * DD + d];
    red[grp][d] = s;
    __syncthreads();
    if (t < 64)
        g_z[b * DD + t] = (red[0][t] + red[1][t] + red[2][t] + red[3][t]) * (1.0f / (float)SS);
}

// ------------------- k4: LayerNorm + classifier + aux loss -----------------
__global__ void k4_cls(const float* __restrict__ lng, const float* __restrict__ lnb,
                       const float* __restrict__ w1,  const float* __restrict__ b1,
                       const float* __restrict__ w2,  const float* __restrict__ b2,
                       float* __restrict__ out, int out_size) {
    int b = threadIdx.x;   // 128
    float zr[DD];
    float s = 0.0f;
#pragma unroll
    for (int d = 0; d < DD; ++d) { float v = g_z[b * DD + d]; zr[d] = v; s += v; }
    float mu = s * (1.0f / DD);
    float ss2 = 0.0f;
#pragma unroll
    for (int d = 0; d < DD; ++d) { float c = zr[d] - mu; ss2 += c * c; }
    float inv = rsqrtf(ss2 * (1.0f / DD) + 1e-5f);
#pragma unroll
    for (int d = 0; d < DD; ++d)
        zr[d] = (zr[d] - mu) * inv * lng[d] + lnb[d];

    float h[DD];
#pragma unroll
    for (int o = 0; o < DD; ++o) h[o] = b1[o];
    for (int d = 0; d < DD; ++d) {
        float zd = zr[d];
#pragma unroll
        for (int o = 0; o < DD; ++o) h[o] += zd * w1[d * DD + o];
    }
#pragma unroll
    for (int o = 0; o < DD; ++o) h[o] = gelu_f(h[o]);

    float y[NCLS];
#pragma unroll
    for (int c = 0; c < NCLS; ++c) y[c] = b2[c];
    for (int o = 0; o < DD; ++o) {
        float ho = h[o];
#pragma unroll
        for (int c = 0; c < NCLS; ++c) y[c] += ho * w2[o * NCLS + c];
    }
#pragma unroll
    for (int c = 0; c < NCLS; ++c) out[b * NCLS + c] = y[c];

    if (b == 0) {
        float aux = 0.0f;
        for (int e = 0; e < EE; ++e) {
            float f = (float)g_cnt[e] / (float)TT;
            float p = g_psum[e] / (float)TT;
            aux += f * p;
        }
        out[out_size - 1] = (float)EE * aux;
    }
}

// ----------------------------- launch ---------------------------------------
extern "C" void kernel_launch(void* const* d_in, const int* in_sizes, int n_in,
                              void* d_out, int out_size) {
    const float* x      = (const float*)d_in[0];
    const float* pe_w1  = (const float*)d_in[1];
    const float* pe_b1  = (const float*)d_in[2];
    const float* pe_w2  = (const float*)d_in[3];
    const float* pe_b2  = (const float*)d_in[4];
    const float* gate_w = (const float*)d_in[5];
    const float* gate_b = (const float*)d_in[6];
    const float* ew1    = (const float*)d_in[7];
    const float* eb1    = (const float*)d_in[8];
    const float* ew2    = (const float*)d_in[9];
    const float* eb2    = (const float*)d_in[10];
    const float* ln_g   = (const float*)d_in[11];
    const float* ln_b   = (const float*)d_in[12];
    const float* cl_w1  = (const float*)d_in[13];
    const float* cl_b1  = (const float*)d_in[14];
    const float* cl_w2  = (const float*)d_in[15];
    const float* cl_b2  = (const float*)d_in[16];

    const int smem1 = (128 * PA2 + 32 * PW2) * 8;            // 51712 B
    const int smem2 = (64 * PH2 + 64 * PW2) * 8;             // 67584 B
    const int smem3 = (2 * 64 * PH2 + 64 * PW2) * 8 + 64 * 8;// 101888 B
    cudaFuncSetAttribute(k1_pe1,      cudaFuncAttributeMaxDynamicSharedMemorySize, smem1);
    cudaFuncSetAttribute(k2_pe2_gate, cudaFuncAttributeMaxDynamicSharedMemorySize, smem2);
    cudaFuncSetAttribute(k3_expert,   cudaFuncAttributeMaxDynamicSharedMemorySize, smem3);

    k0_zero<<<1, 32>>>();
    k1_pe1<<<TT / 128, 256, smem1>>>(x, pe_w1, pe_b1);
    k2_pe2_gate<<<TT / 64, 256, smem2>>>(pe_w2, pe_b2, gate_w, gate_b);
    k3_expert<<<dim3(TT / 64, EE), 256, smem3>>>(ew1, eb1, ew2, eb2);
    k3b_reduce<<<BB, 256>>>();
    k4_cls<<<1, 128>>>(ln_g, ln_b, cl_w1, cl_b1, cl_w2, cl_b2,
                       (float*)d_out, out_size);
}